// round 12
// baseline (speedup 1.0000x reference)
#include <cuda_runtime.h>
#include <cuda_bf16.h>
#include <cstdint>

#define B_  4
#define T_  2048
#define C_  1024
#define H_  16
#define HD_ 64
#define BH_ (B_*H_)
#define KD_ 1024

// ---------------------------------------------------------------------------
// Device-global scratch
// ---------------------------------------------------------------------------
__device__ __nv_bfloat16 g_Qh[(size_t)BH_*T_*HD_], g_Ql[(size_t)BH_*T_*HD_];
__device__ __nv_bfloat16 g_Kh[(size_t)BH_*T_*HD_], g_Kl[(size_t)BH_*T_*HD_];
__device__ __nv_bfloat16 g_Vh[(size_t)BH_*T_*HD_], g_Vl[(size_t)BH_*T_*HD_];

__device__ __nv_bfloat16 g_Xhi[(size_t)B_*T_*C_],   g_Xlo[(size_t)B_*T_*C_];
__device__ __nv_bfloat16 g_Wahi[(size_t)3*C_*C_],   g_Walo[(size_t)3*C_*C_];
__device__ __nv_bfloat16 g_Wphi[(size_t)C_*C_],     g_Wplo[(size_t)C_*C_];
__device__ __nv_bfloat16 g_Ohi[(size_t)B_*T_*C_],   g_Olo[(size_t)B_*T_*C_];

// ---------------------------------------------------------------------------
// Helpers
// ---------------------------------------------------------------------------
__device__ __forceinline__ uint32_t smem_u32(const void* p) {
    uint32_t a;
    asm("{ .reg .u64 t; cvta.to.shared.u64 t, %1; cvt.u32.u64 %0, t; }"
        : "=r"(a) : "l"(p));
    return a;
}

#define CP_ASYNC16(dst, src) \
    asm volatile("cp.async.cg.shared.global [%0], [%1], 16;" :: "r"(dst), "l"(src))
#define CP_COMMIT() asm volatile("cp.async.commit_group;" ::: "memory")
#define CP_WAIT1()  asm volatile("cp.async.wait_group 1;" ::: "memory")
#define CP_WAIT0()  asm volatile("cp.async.wait_group 0;" ::: "memory")

#define LDSM_X4(r0, r1, r2, r3, addr) \
    asm volatile("ldmatrix.sync.aligned.m8n8.x4.shared.b16 {%0,%1,%2,%3}, [%4];" \
        : "=r"(r0), "=r"(r1), "=r"(r2), "=r"(r3) : "r"(addr))
#define LDSM_X4_T(r0, r1, r2, r3, addr) \
    asm volatile("ldmatrix.sync.aligned.m8n8.x4.trans.shared.b16 {%0,%1,%2,%3}, [%4];" \
        : "=r"(r0), "=r"(r1), "=r"(r2), "=r"(r3) : "r"(addr))

#define MMA_(c, a0, a1, a2, a3, b0, b1) \
    asm volatile("mma.sync.aligned.m16n8k16.row.col.f32.bf16.bf16.f32 " \
        "{%0,%1,%2,%3}, {%4,%5,%6,%7}, {%8,%9}, {%0,%1,%2,%3};" \
        : "+f"((c)[0]), "+f"((c)[1]), "+f"((c)[2]), "+f"((c)[3]) \
        : "r"(a0), "r"(a1), "r"(a2), "r"(a3), "r"(b0), "r"(b1))

__device__ __forceinline__ uint32_t pack_bf16(float lo, float hi) {
    uint32_t r;
    asm("cvt.rn.bf16x2.f32 %0, %1, %2;" : "=r"(r) : "f"(hi), "f"(lo));
    return r;
}
__device__ __forceinline__ float bf16lo_f(uint32_t r) { return __int_as_float(r << 16); }
__device__ __forceinline__ float bf16hi_f(uint32_t r) { return __int_as_float(r & 0xffff0000u); }

// exp via MUFU pipe.
__device__ __forceinline__ float fexp(float x) {
    float y;
    asm("ex2.approx.ftz.f32 %0, %1;" : "=f"(y) : "f"(x * 1.4426950408889634f));
    return y;
}

// Swizzled 64B-row offset (GEMM): phys chunk = ch ^ ((row>>1)&3)
__device__ __forceinline__ uint32_t sw64(int row, int ch) {
    return (uint32_t)(row * 64 + ((ch ^ ((row >> 1) & 3)) << 4));
}
// Swizzled 128B-row offset (attention): phys chunk = ch ^ (row&7)
__device__ __forceinline__ uint32_t sw128r(int row, int ch) {
    return (uint32_t)(row * 128 + ((ch ^ (row & 7)) << 4));
}

// ---------------------------------------------------------------------------
// Kernel A: fused fp32 -> bf16 hi/lo split for x, W_attn, W_proj.
// ---------------------------------------------------------------------------
#define NX4   ((B_*T_*C_) / 4)
#define NWA4  ((3*C_*C_) / 4)
#define NWP4  ((C_*C_) / 4)

__global__ void __launch_bounds__(256) split_all_kernel(
    const float4* __restrict__ x, const float4* __restrict__ wa,
    const float4* __restrict__ wp)
{
    size_t i = (size_t)blockIdx.x * blockDim.x + threadIdx.x;
    const float4* src;
    __nv_bfloat16 *hi, *lo;
    size_t j;
    if (i < NX4)                 { src = x;  j = i;               hi = g_Xhi;  lo = g_Xlo;  }
    else if (i < NX4 + NWA4)     { src = wa; j = i - NX4;         hi = g_Wahi; lo = g_Walo; }
    else                         { src = wp; j = i - NX4 - NWA4;  hi = g_Wphi; lo = g_Wplo; }

    float4 v = src[j];
    __nv_bfloat16 hx = __float2bfloat16(v.x), hy = __float2bfloat16(v.y);
    __nv_bfloat16 hz = __float2bfloat16(v.z), hw = __float2bfloat16(v.w);
    __nv_bfloat16 lx = __float2bfloat16(v.x - __bfloat162float(hx));
    __nv_bfloat16 ly = __float2bfloat16(v.y - __bfloat162float(hy));
    __nv_bfloat16 lz = __float2bfloat16(v.z - __bfloat162float(hz));
    __nv_bfloat16 lw = __float2bfloat16(v.w - __bfloat162float(hw));
    __nv_bfloat162* Hh = reinterpret_cast<__nv_bfloat162*>(hi + 4 * j);
    __nv_bfloat162* Ll = reinterpret_cast<__nv_bfloat162*>(lo + 4 * j);
    Hh[0] = __halves2bfloat162(hx, hy); Hh[1] = __halves2bfloat162(hz, hw);
    Ll[0] = __halves2bfloat162(lx, ly); Ll[1] = __halves2bfloat162(lz, lw);
}

// ---------------------------------------------------------------------------
// Kernel B: HMMA split GEMM, templated on M-tile (MT=64 for QKV, MT=32 for
// proj to fix wave quantization). 3-buffer / 2-deep cp.async pipeline,
// one barrier per chunk (R9-validated schedule).
// ---------------------------------------------------------------------------
#define BK_      32
#define GB_TILE  8192

template<int MT>
__global__ void __launch_bounds__(256, 3) hmma_gemm_kernel(
    const float* __restrict__ bias, float* __restrict__ Cout, int mode)
{
    constexpr int MI      = MT / 32;             // m sub-tiles per warp
    constexpr int WROWS   = MT / 2;              // rows per m-warp
    constexpr int GA_TILE = MT * 64;             // bytes per A tile
    constexpr int GSTAGE  = 2 * GA_TILE + 2 * GB_TILE;
    constexpr int NIT     = (8 * MT + 4096) / 1024 / (256 / 64); // transfers/256thr
    // NIT: total 16B transfers per chunk = (2*MT*4 + 2*128*4) = 8MT+1024; /256.
    constexpr int NTR     = (8 * MT + 1024) / 256;

    extern __shared__ __align__(128) char smem[];
    const __nv_bfloat16 *Ahi, *Alo, *Bhi, *Blo;
    if (mode == 0) { Ahi = g_Xhi; Alo = g_Xlo; Bhi = g_Wahi; Blo = g_Walo; }
    else           { Ahi = g_Ohi; Alo = g_Olo; Bhi = g_Wphi; Blo = g_Wplo; }

    uint32_t sb = smem_u32(smem);
    int tid = threadIdx.x, lane = tid & 31, wid = tid >> 5;
    int bm = blockIdx.y * MT, bn = blockIdx.x * 128;
    int wm = wid >> 2;
    int wn = wid & 3;

    auto prefetch = [&](int chunk, int stage) {
        int k0 = chunk * BK_;
        uint32_t sbase = sb + stage * GSTAGE;
#pragma unroll
        for (int it = 0; it < NTR; it++) {
            int idx = tid + it * 256;
            if (idx < 8 * MT) {
                int row = idx >> 2, ch = idx & 3;
                int r = row & (MT - 1);
                const __nv_bfloat16* src =
                    ((row < MT) ? Ahi : Alo) + (size_t)(bm + r) * KD_ + k0 + ch * 8;
                CP_ASYNC16(sbase + ((row < MT) ? 0 : GA_TILE) + sw64(r, ch), src);
            } else {
                int j = idx - 8 * MT;
                int row = j >> 2, ch = j & 3;
                int r = row & 127;
                const __nv_bfloat16* src =
                    ((row < 128) ? Bhi : Blo) + (size_t)(bn + r) * KD_ + k0 + ch * 8;
                CP_ASYNC16(sbase + 2 * GA_TILE + ((row < 128) ? 0 : GB_TILE) + sw64(r, ch), src);
            }
        }
        CP_COMMIT();
    };
    (void)sizeof(char[NIT >= 0 ? 1 : 1]); // silence unused constexpr

    float acc[MI][4][4];
#pragma unroll
    for (int mi = 0; mi < MI; mi++)
#pragma unroll
        for (int ni = 0; ni < 4; ni++)
#pragma unroll
            for (int r = 0; r < 4; r++) acc[mi][ni][r] = 0.f;

    prefetch(0, 0);
    prefetch(1, 1);

    const int NCH = KD_ / BK_;   // 32
    for (int ch = 0; ch < NCH; ch++) {
        if (ch < NCH - 1) CP_WAIT1(); else CP_WAIT0();
        __syncthreads();

        int stage = ch - (ch / 3) * 3;
        uint32_t sbase = sb + stage * GSTAGE;
        uint32_t bbase = sbase + 2 * GA_TILE;

        if (ch + 2 < NCH) {
            int pst = ch + 2 - ((ch + 2) / 3) * 3;
            prefetch(ch + 2, pst);
        }

#pragma unroll
        for (int ks = 0; ks < 2; ks++) {
            uint32_t ah[MI][4], al[MI][4], bh[2][4], bl[2][4];
            int ac = ks * 2 + (lane >> 4);
#pragma unroll
            for (int mi = 0; mi < MI; mi++) {
                int ar = wm * WROWS + mi * 16 + (lane & 15);
                uint32_t ad = sbase + sw64(ar, ac);
                LDSM_X4(ah[mi][0], ah[mi][1], ah[mi][2], ah[mi][3], ad);
                LDSM_X4(al[mi][0], al[mi][1], al[mi][2], al[mi][3], ad + GA_TILE);
            }
            int bc = ks * 2 + ((lane >> 3) & 1);
            int brl = ((lane >> 4) << 3) + (lane & 7);
#pragma unroll
            for (int np = 0; np < 2; np++) {
                int br = wn * 32 + np * 16 + brl;
                uint32_t bd = bbase + sw64(br, bc);
                LDSM_X4(bh[np][0], bh[np][1], bh[np][2], bh[np][3], bd);
                LDSM_X4(bl[np][0], bl[np][1], bl[np][2], bl[np][3], bd + GB_TILE);
            }
#pragma unroll
            for (int mi = 0; mi < MI; mi++)
#pragma unroll
                for (int np = 0; np < 2; np++) {
                    MMA_(acc[mi][2*np],   ah[mi][0], ah[mi][1], ah[mi][2], ah[mi][3], bh[np][0], bh[np][1]);
                    MMA_(acc[mi][2*np+1], ah[mi][0], ah[mi][1], ah[mi][2], ah[mi][3], bh[np][2], bh[np][3]);
                }
#pragma unroll
            for (int mi = 0; mi < MI; mi++)
#pragma unroll
                for (int np = 0; np < 2; np++) {
                    MMA_(acc[mi][2*np],   ah[mi][0], ah[mi][1], ah[mi][2], ah[mi][3], bl[np][0], bl[np][1]);
                    MMA_(acc[mi][2*np+1], ah[mi][0], ah[mi][1], ah[mi][2], ah[mi][3], bl[np][2], bl[np][3]);
                }
#pragma unroll
            for (int mi = 0; mi < MI; mi++)
#pragma unroll
                for (int np = 0; np < 2; np++) {
                    MMA_(acc[mi][2*np],   al[mi][0], al[mi][1], al[mi][2], al[mi][3], bh[np][0], bh[np][1]);
                    MMA_(acc[mi][2*np+1], al[mi][0], al[mi][1], al[mi][2], al[mi][3], bh[np][2], bh[np][3]);
                }
        }
    }

    int g = lane >> 2, t = lane & 3;
    if (mode == 0) {
#pragma unroll
        for (int mi = 0; mi < MI; mi++)
#pragma unroll
            for (int ni = 0; ni < 4; ni++) {
                int c0 = bn + wn * 32 + ni * 8 + t * 2;
                int seg = c0 >> 10, cn = c0 & 1023;
                int h = cn >> 6, d = cn & 63;
                float b0 = bias[c0], b1 = bias[c0 + 1];
#pragma unroll
                for (int half = 0; half < 2; half++) {
                    int m = bm + wm * WROWS + mi * 16 + g + half * 8;
                    int b = m >> 11, tt = m & 2047;
                    float v0 = acc[mi][ni][half * 2 + 0] + b0;
                    float v1 = acc[mi][ni][half * 2 + 1] + b1;
                    if (seg == 0) { v0 *= 0.125f; v1 *= 0.125f; }
                    uint32_t hp = pack_bf16(v0, v1);
                    uint32_t lp = pack_bf16(v0 - bf16lo_f(hp), v1 - bf16hi_f(hp));
                    size_t o = (((size_t)(b * H_ + h) * T_) + tt) * HD_ + d;
                    __nv_bfloat16 *dh, *dl;
                    if (seg == 0)      { dh = g_Qh; dl = g_Ql; }
                    else if (seg == 1) { dh = g_Kh; dl = g_Kl; }
                    else               { dh = g_Vh; dl = g_Vl; }
                    *reinterpret_cast<uint32_t*>(dh + o) = hp;
                    *reinterpret_cast<uint32_t*>(dl + o) = lp;
                }
            }
    } else {
#pragma unroll
        for (int mi = 0; mi < MI; mi++)
#pragma unroll
            for (int ni = 0; ni < 4; ni++) {
                int r0 = bm + wm * WROWS + mi * 16 + g;
                int c0 = bn + wn * 32 + ni * 8 + t * 2;
                float2 v0 = make_float2(acc[mi][ni][0] + bias[c0],
                                        acc[mi][ni][1] + bias[c0 + 1]);
                float2 v1 = make_float2(acc[mi][ni][2] + bias[c0],
                                        acc[mi][ni][3] + bias[c0 + 1]);
                *reinterpret_cast<float2*>(&Cout[(size_t)r0 * C_ + c0]) = v0;
                *reinterpret_cast<float2*>(&Cout[(size_t)(r0 + 8) * C_ + c0]) = v1;
            }
    }
}

#define GEMM_SMEM_64 (3 * (2 * 64 * 64 + 2 * GB_TILE))   // 73728
#define GEMM_SMEM_32 (3 * (2 * 32 * 64 + 2 * GB_TILE))   // 61440

// ---------------------------------------------------------------------------
// Kernel C: flash attention, 128 queries per CTA (two 64-row subtiles),
// 3-buffer / 2-deep KV cp.async ring (wait_group 1).
// ---------------------------------------------------------------------------
#define KV_TILE  8192
#define KV_STAGE (4 * KV_TILE)               // 32768
#define ATTN_SMEM_BYTES (3 * KV_STAGE)       // 98304

__global__ void __launch_bounds__(128, 2) attn_hmma_kernel()
{
    extern __shared__ __align__(128) char smem[];
    uint32_t sb = smem_u32(smem);
    int tid = threadIdx.x, lane = tid & 31, wid = tid >> 5;
    int bh = blockIdx.y, q0 = blockIdx.x * 128;
    size_t bhbase = (size_t)bh * T_ * HD_;

    // ---- stage 128 Q rows (hi at [0,16K), lo at [16K,32K)), consume to regs
    {
        const __nv_bfloat16* Qh = g_Qh + bhbase + (size_t)q0 * HD_;
        const __nv_bfloat16* Ql = g_Ql + bhbase + (size_t)q0 * HD_;
#pragma unroll
        for (int it = 0; it < 16; it++) {
            int idx = tid + it * 128;
            int tile = idx >> 10, within = idx & 1023;
            int row = within >> 3, ch = within & 7;
            const __nv_bfloat16* src = (tile ? Ql : Qh) + (size_t)row * HD_ + ch * 8;
            CP_ASYNC16(sb + tile * 16384 + sw128r(row, ch), src);
        }
        CP_COMMIT(); CP_WAIT0();
        __syncthreads();
    }

    uint32_t qh[2][4][4], ql[2][4][4];
#pragma unroll
    for (int sub = 0; sub < 2; sub++) {
        int arow = sub * 64 + wid * 16 + (lane & 15);
#pragma unroll
        for (int ks = 0; ks < 4; ks++) {
            int ac = ks * 2 + (lane >> 4);
            uint32_t addr = sb + sw128r(arow, ac);
            LDSM_X4(qh[sub][ks][0], qh[sub][ks][1], qh[sub][ks][2], qh[sub][ks][3], addr);
            LDSM_X4(ql[sub][ks][0], ql[sub][ks][1], ql[sub][ks][2], ql[sub][ks][3], addr + 16384);
        }
    }
    __syncthreads();   // Q consumed; KV ring may overwrite

    const __nv_bfloat16 *Kh = g_Kh + bhbase, *Kl = g_Kl + bhbase;
    const __nv_bfloat16 *Vh = g_Vh + bhbase, *Vl = g_Vl + bhbase;

    auto kv_prefetch = [&](int kt) {
        int stage = kt - (kt / 3) * 3;
        uint32_t sbase = sb + stage * KV_STAGE;
        int k0 = kt * 64;
#pragma unroll
        for (int it = 0; it < 16; it++) {
            int idx = tid + it * 128;
            int tile = idx >> 9, within = idx & 511;
            int row = within >> 3, ch = within & 7;
            const __nv_bfloat16* base =
                (tile == 0) ? Kh : (tile == 1) ? Kl : (tile == 2) ? Vh : Vl;
            CP_ASYNC16(sbase + tile * KV_TILE + sw128r(row, ch),
                       base + (size_t)(k0 + row) * HD_ + ch * 8);
        }
        CP_COMMIT();
    };

    float o[2][8][4];
#pragma unroll
    for (int sub = 0; sub < 2; sub++)
#pragma unroll
        for (int j = 0; j < 8; j++)
#pragma unroll
            for (int r = 0; r < 4; r++) o[sub][j][r] = 0.f;
    float mrow[2][2] = {{-1e30f, -1e30f}, {-1e30f, -1e30f}};
    float lrow[2][2] = {{0.f, 0.f}, {0.f, 0.f}};

    kv_prefetch(0);
    kv_prefetch(1);

    const int NT = T_ / 64;   // 32
    for (int kt = 0; kt < NT; kt++) {
        if (kt < NT - 1) CP_WAIT1(); else CP_WAIT0();
        __syncthreads();   // tile kt visible; tile kt-1 retired by all warps

        int stage = kt - (kt / 3) * 3;
        uint32_t sbase = sb + stage * KV_STAGE;
        uint32_t vbase = sbase + 2 * KV_TILE;

        // prefetch kt+2 into stage (kt-1)%3 (retired at barrier above)
        if (kt + 2 < NT) kv_prefetch(kt + 2);

        int brl = ((lane >> 4) << 3) + (lane & 7);
        int bc  = (lane >> 3) & 1;
        int vrow = lane & 15;
        int vc = lane >> 4;

#pragma unroll
        for (int sub = 0; sub < 2; sub++) {
            // ---- S = Q K^T for this subtile ----
            float s[8][4];
#pragma unroll
            for (int j = 0; j < 8; j++)
#pragma unroll
                for (int r = 0; r < 4; r++) s[j][r] = 0.f;

#pragma unroll
            for (int ks = 0; ks < 4; ks++) {
                int lc = ks * 2 + bc;
#pragma unroll
                for (int npp = 0; npp < 2; npp++) {
                    int r0 = (2 * npp) * 16 + brl;
                    int r1 = (2 * npp + 1) * 16 + brl;
                    uint32_t a0 = sbase + sw128r(r0, lc);
                    uint32_t a1 = sbase + sw128r(r1, lc);
                    uint32_t kh0[4], kh1[4], kl0[4], kl1[4];
                    LDSM_X4(kh0[0], kh0[1], kh0[2], kh0[3], a0);
                    LDSM_X4(kh1[0], kh1[1], kh1[2], kh1[3], a1);
                    LDSM_X4(kl0[0], kl0[1], kl0[2], kl0[3], a0 + KV_TILE);
                    LDSM_X4(kl1[0], kl1[1], kl1[2], kl1[3], a1 + KV_TILE);
                    float* s0 = s[4*npp+0]; float* s1 = s[4*npp+1];
                    float* s2 = s[4*npp+2]; float* s3 = s[4*npp+3];
                    const uint32_t* QH = qh[sub][ks];
                    const uint32_t* QL = ql[sub][ks];
                    MMA_(s0, QH[0], QH[1], QH[2], QH[3], kh0[0], kh0[1]);
                    MMA_(s1, QH[0], QH[1], QH[2], QH[3], kh0[2], kh0[3]);
                    MMA_(s2, QH[0], QH[1], QH[2], QH[3], kh1[0], kh1[1]);
                    MMA_(s3, QH[0], QH[1], QH[2], QH[3], kh1[2], kh1[3]);
                    MMA_(s0, QH[0], QH[1], QH[2], QH[3], kl0[0], kl0[1]);
                    MMA_(s1, QH[0], QH[1], QH[2], QH[3], kl0[2], kl0[3]);
                    MMA_(s2, QH[0], QH[1], QH[2], QH[3], kl1[0], kl1[1]);
                    MMA_(s3, QH[0], QH[1], QH[2], QH[3], kl1[2], kl1[3]);
                    MMA_(s0, QL[0], QL[1], QL[2], QL[3], kh0[0], kh0[1]);
                    MMA_(s1, QL[0], QL[1], QL[2], QL[3], kh0[2], kh0[3]);
                    MMA_(s2, QL[0], QL[1], QL[2], QL[3], kh1[0], kh1[1]);
                    MMA_(s3, QL[0], QL[1], QL[2], QL[3], kh1[2], kh1[3]);
                }
            }

            // ---- online softmax ----
            float mt0 = -1e30f, mt1 = -1e30f;
#pragma unroll
            for (int j = 0; j < 8; j++) {
                mt0 = fmaxf(mt0, fmaxf(s[j][0], s[j][1]));
                mt1 = fmaxf(mt1, fmaxf(s[j][2], s[j][3]));
            }
            mt0 = fmaxf(mt0, __shfl_xor_sync(0xffffffffu, mt0, 1));
            mt0 = fmaxf(mt0, __shfl_xor_sync(0xffffffffu, mt0, 2));
            mt1 = fmaxf(mt1, __shfl_xor_sync(0xffffffffu, mt1, 1));
            mt1 = fmaxf(mt1, __shfl_xor_sync(0xffffffffu, mt1, 2));
            float mn0 = fmaxf(mrow[sub][0], mt0), mn1 = fmaxf(mrow[sub][1], mt1);
            float corr0 = fexp(mrow[sub][0] - mn0), corr1 = fexp(mrow[sub][1] - mn1);
            float sum0 = 0.f, sum1 = 0.f;
#pragma unroll
            for (int j = 0; j < 8; j++) {
                s[j][0] = fexp(s[j][0] - mn0);
                s[j][1] = fexp(s[j][1] - mn0);
                s[j][2] = fexp(s[j][2] - mn1);
                s[j][3] = fexp(s[j][3] - mn1);
                sum0 += s[j][0] + s[j][1];
                sum1 += s[j][2] + s[j][3];
            }
            sum0 += __shfl_xor_sync(0xffffffffu, sum0, 1);
            sum0 += __shfl_xor_sync(0xffffffffu, sum0, 2);
            sum1 += __shfl_xor_sync(0xffffffffu, sum1, 1);
            sum1 += __shfl_xor_sync(0xffffffffu, sum1, 2);
            lrow[sub][0] = lrow[sub][0] * corr0 + sum0;
            lrow[sub][1] = lrow[sub][1] * corr1 + sum1;
            mrow[sub][0] = mn0; mrow[sub][1] = mn1;
#pragma unroll
            for (int j = 0; j < 8; j++) {
                o[sub][j][0] *= corr0; o[sub][j][1] *= corr0;
                o[sub][j][2] *= corr1; o[sub][j][3] *= corr1;
            }

            // ---- O += P V ----
#pragma unroll
            for (int ks = 0; ks < 4; ks++) {
                uint32_t ah0 = pack_bf16(s[2*ks][0],   s[2*ks][1]);
                uint32_t ah1 = pack_bf16(s[2*ks][2],   s[2*ks][3]);
                uint32_t ah2 = pack_bf16(s[2*ks+1][0], s[2*ks+1][1]);
                uint32_t ah3 = pack_bf16(s[2*ks+1][2], s[2*ks+1][3]);
                uint32_t al0 = pack_bf16(s[2*ks][0]   - bf16lo_f(ah0), s[2*ks][1]   - bf16hi_f(ah0));
                uint32_t al1 = pack_bf16(s[2*ks][2]   - bf16lo_f(ah1), s[2*ks][3]   - bf16hi_f(ah1));
                uint32_t al2 = pack_bf16(s[2*ks+1][0] - bf16lo_f(ah2), s[2*ks+1][1] - bf16hi_f(ah2));
                uint32_t al3 = pack_bf16(s[2*ks+1][2] - bf16lo_f(ah3), s[2*ks+1][3] - bf16hi_f(ah3));
                int row = ks * 16 + vrow;
#pragma unroll
                for (int jpp = 0; jpp < 2; jpp++) {
                    int lc0 = (2 * jpp) * 2 + vc;
                    int lc1 = (2 * jpp + 1) * 2 + vc;
                    uint32_t a0 = vbase + sw128r(row, lc0);
                    uint32_t a1 = vbase + sw128r(row, lc1);
                    uint32_t vh0[4], vh1[4], vl0[4], vl1[4];
                    LDSM_X4_T(vh0[0], vh0[1], vh0[2], vh0[3], a0);
                    LDSM_X4_T(vh1[0], vh1[1], vh1[2], vh1[3], a1);
                    LDSM_X4_T(vl0[0], vl0[1], vl0[2], vl0[3], a0 + KV_TILE);
                    LDSM_X4_T(vl1[0], vl1[1], vl1[2], vl1[3], a1 + KV_TILE);
                    float* o0 = o[sub][4*jpp+0]; float* o1 = o[sub][4*jpp+1];
                    float* o2 = o[sub][4*jpp+2]; float* o3 = o[sub][4*jpp+3];
                    MMA_(o0, ah0, ah1, ah2, ah3, vh0[0], vh0[1]);
                    MMA_(o1, ah0, ah1, ah2, ah3, vh0[2], vh0[3]);
                    MMA_(o2, ah0, ah1, ah2, ah3, vh1[0], vh1[1]);
                    MMA_(o3, ah0, ah1, ah2, ah3, vh1[2], vh1[3]);
                    MMA_(o0, ah0, ah1, ah2, ah3, vl0[0], vl0[1]);
                    MMA_(o1, ah0, ah1, ah2, ah3, vl0[2], vl0[3]);
                    MMA_(o2, ah0, ah1, ah2, ah3, vl1[0], vl1[1]);
                    MMA_(o3, ah0, ah1, ah2, ah3, vl1[2], vl1[3]);
                    MMA_(o0, al0, al1, al2, al3, vh0[0], vh0[1]);
                    MMA_(o1, al0, al1, al2, al3, vh0[2], vh0[3]);
                    MMA_(o2, al0, al1, al2, al3, vh1[0], vh1[1]);
                    MMA_(o3, al0, al1, al2, al3, vh1[2], vh1[3]);
                }
            }
        }
    }

    // ---- finalize ----
    int g = lane >> 2, t = lane & 3;
    int b = bh >> 4, h = bh & 15;
#pragma unroll
    for (int sub = 0; sub < 2; sub++) {
        float inv0 = 1.0f / lrow[sub][0], inv1 = 1.0f / lrow[sub][1];
        int row0 = q0 + sub * 64 + wid * 16 + g;
        size_t ob0 = ((size_t)(b * T_) + row0) * C_ + h * 64 + t * 2;
        size_t ob1 = ob0 + (size_t)8 * C_;
#pragma unroll
        for (int j = 0; j < 8; j++) {
            float v0 = o[sub][j][0] * inv0, v1 = o[sub][j][1] * inv0;
            float v2 = o[sub][j][2] * inv1, v3 = o[sub][j][3] * inv1;
            uint32_t h0 = pack_bf16(v0, v1);
            uint32_t h1 = pack_bf16(v2, v3);
            uint32_t l0p = pack_bf16(v0 - bf16lo_f(h0), v1 - bf16hi_f(h0));
            uint32_t l1p = pack_bf16(v2 - bf16lo_f(h1), v3 - bf16hi_f(h1));
            *reinterpret_cast<uint32_t*>(g_Ohi + ob0 + j * 8) = h0;
            *reinterpret_cast<uint32_t*>(g_Ohi + ob1 + j * 8) = h1;
            *reinterpret_cast<uint32_t*>(g_Olo + ob0 + j * 8) = l0p;
            *reinterpret_cast<uint32_t*>(g_Olo + ob1 + j * 8) = l1p;
        }
    }
}

// ---------------------------------------------------------------------------
extern "C" void kernel_launch(void* const* d_in, const int* in_sizes, int n_in,
                              void* d_out, int out_size)
{
    const float* x      = (const float*)d_in[0];
    const float* W_attn = (const float*)d_in[1];
    const float* b_attn = (const float*)d_in[2];
    const float* W_proj = (const float*)d_in[3];
    const float* b_proj = (const float*)d_in[4];
    float* out = (float*)d_out;

    cudaFuncSetAttribute(hmma_gemm_kernel<64>,
                         cudaFuncAttributeMaxDynamicSharedMemorySize, GEMM_SMEM_64);
    cudaFuncSetAttribute(hmma_gemm_kernel<32>,
                         cudaFuncAttributeMaxDynamicSharedMemorySize, GEMM_SMEM_32);
    cudaFuncSetAttribute(attn_hmma_kernel,
                         cudaFuncAttributeMaxDynamicSharedMemorySize, ATTN_SMEM_BYTES);

    int splitBlocks = (NX4 + NWA4 + NWP4) / 256;
    split_all_kernel<<<splitBlocks, 256>>>(
        (const float4*)x, (const float4*)W_attn, (const float4*)W_proj);

    // QKV: MT=64, grid (24, 128)
    hmma_gemm_kernel<64><<<dim3(3 * C_ / 128, B_ * T_ / 64), 256, GEMM_SMEM_64>>>(
        b_attn, nullptr, 0);

    attn_hmma_kernel<<<dim3(T_ / 128, BH_), 128, ATTN_SMEM_BYTES>>>();

    // proj: MT=32, grid (8, 256) -> 2048 CTAs, better wave packing
    hmma_gemm_kernel<32><<<dim3(C_ / 128, B_ * T_ / 32), 256, GEMM_SMEM_32>>>(
        b_proj, out, 1);
}

// round 13
// speedup vs baseline: 1.1120x; 1.1120x over previous
#include <cuda_runtime.h>
#include <cuda_bf16.h>
#include <cstdint>

#define B_  4
#define T_  2048
#define C_  1024
#define H_  16
#define HD_ 64
#define BH_ (B_*H_)
#define KD_ 1024

// ---------------------------------------------------------------------------
// Device-global scratch
// ---------------------------------------------------------------------------
__device__ __nv_bfloat16 g_Qh[(size_t)BH_*T_*HD_], g_Ql[(size_t)BH_*T_*HD_];
__device__ __nv_bfloat16 g_Kh[(size_t)BH_*T_*HD_], g_Kl[(size_t)BH_*T_*HD_];
__device__ __nv_bfloat16 g_Vh[(size_t)BH_*T_*HD_], g_Vl[(size_t)BH_*T_*HD_];

__device__ __nv_bfloat16 g_Xhi[(size_t)B_*T_*C_],   g_Xlo[(size_t)B_*T_*C_];
__device__ __nv_bfloat16 g_Wahi[(size_t)3*C_*C_],   g_Walo[(size_t)3*C_*C_];
__device__ __nv_bfloat16 g_Wphi[(size_t)C_*C_],     g_Wplo[(size_t)C_*C_];
__device__ __nv_bfloat16 g_Ohi[(size_t)B_*T_*C_],   g_Olo[(size_t)B_*T_*C_];

// ---------------------------------------------------------------------------
// Helpers
// ---------------------------------------------------------------------------
__device__ __forceinline__ uint32_t smem_u32(const void* p) {
    uint32_t a;
    asm("{ .reg .u64 t; cvta.to.shared.u64 t, %1; cvt.u32.u64 %0, t; }"
        : "=r"(a) : "l"(p));
    return a;
}

#define CP_ASYNC16(dst, src) \
    asm volatile("cp.async.cg.shared.global [%0], [%1], 16;" :: "r"(dst), "l"(src))
#define CP_COMMIT() asm volatile("cp.async.commit_group;" ::: "memory")
#define CP_WAIT1()  asm volatile("cp.async.wait_group 1;" ::: "memory")
#define CP_WAIT0()  asm volatile("cp.async.wait_group 0;" ::: "memory")

#define LDSM_X4(r0, r1, r2, r3, addr) \
    asm volatile("ldmatrix.sync.aligned.m8n8.x4.shared.b16 {%0,%1,%2,%3}, [%4];" \
        : "=r"(r0), "=r"(r1), "=r"(r2), "=r"(r3) : "r"(addr))
#define LDSM_X4_T(r0, r1, r2, r3, addr) \
    asm volatile("ldmatrix.sync.aligned.m8n8.x4.trans.shared.b16 {%0,%1,%2,%3}, [%4];" \
        : "=r"(r0), "=r"(r1), "=r"(r2), "=r"(r3) : "r"(addr))

#define MMA_(c, a0, a1, a2, a3, b0, b1) \
    asm volatile("mma.sync.aligned.m16n8k16.row.col.f32.bf16.bf16.f32 " \
        "{%0,%1,%2,%3}, {%4,%5,%6,%7}, {%8,%9}, {%0,%1,%2,%3};" \
        : "+f"((c)[0]), "+f"((c)[1]), "+f"((c)[2]), "+f"((c)[3]) \
        : "r"(a0), "r"(a1), "r"(a2), "r"(a3), "r"(b0), "r"(b1))

__device__ __forceinline__ uint32_t pack_bf16(float lo, float hi) {
    uint32_t r;
    asm("cvt.rn.bf16x2.f32 %0, %1, %2;" : "=r"(r) : "f"(hi), "f"(lo));
    return r;
}
__device__ __forceinline__ float bf16lo_f(uint32_t r) { return __int_as_float(r << 16); }
__device__ __forceinline__ float bf16hi_f(uint32_t r) { return __int_as_float(r & 0xffff0000u); }

// exp via MUFU pipe.
__device__ __forceinline__ float fexp(float x) {
    float y;
    asm("ex2.approx.ftz.f32 %0, %1;" : "=f"(y) : "f"(x * 1.4426950408889634f));
    return y;
}

// Swizzled 64B-row offset (GEMM): phys chunk = ch ^ ((row>>1)&3)
__device__ __forceinline__ uint32_t sw64(int row, int ch) {
    return (uint32_t)(row * 64 + ((ch ^ ((row >> 1) & 3)) << 4));
}
// Swizzled 128B-row offset (attention): phys chunk = ch ^ (row&7)
__device__ __forceinline__ uint32_t sw128r(int row, int ch) {
    return (uint32_t)(row * 128 + ((ch ^ (row & 7)) << 4));
}

// ---------------------------------------------------------------------------
// Kernel A: fused fp32 -> bf16 hi/lo split for x, W_attn, W_proj.
// ---------------------------------------------------------------------------
#define NX4   ((B_*T_*C_) / 4)
#define NWA4  ((3*C_*C_) / 4)
#define NWP4  ((C_*C_) / 4)

__global__ void __launch_bounds__(256) split_all_kernel(
    const float4* __restrict__ x, const float4* __restrict__ wa,
    const float4* __restrict__ wp)
{
    size_t i = (size_t)blockIdx.x * blockDim.x + threadIdx.x;
    const float4* src;
    __nv_bfloat16 *hi, *lo;
    size_t j;
    if (i < NX4)                 { src = x;  j = i;               hi = g_Xhi;  lo = g_Xlo;  }
    else if (i < NX4 + NWA4)     { src = wa; j = i - NX4;         hi = g_Wahi; lo = g_Walo; }
    else                         { src = wp; j = i - NX4 - NWA4;  hi = g_Wphi; lo = g_Wplo; }

    float4 v = src[j];
    __nv_bfloat16 hx = __float2bfloat16(v.x), hy = __float2bfloat16(v.y);
    __nv_bfloat16 hz = __float2bfloat16(v.z), hw = __float2bfloat16(v.w);
    __nv_bfloat16 lx = __float2bfloat16(v.x - __bfloat162float(hx));
    __nv_bfloat16 ly = __float2bfloat16(v.y - __bfloat162float(hy));
    __nv_bfloat16 lz = __float2bfloat16(v.z - __bfloat162float(hz));
    __nv_bfloat16 lw = __float2bfloat16(v.w - __bfloat162float(hw));
    __nv_bfloat162* Hh = reinterpret_cast<__nv_bfloat162*>(hi + 4 * j);
    __nv_bfloat162* Ll = reinterpret_cast<__nv_bfloat162*>(lo + 4 * j);
    Hh[0] = __halves2bfloat162(hx, hy); Hh[1] = __halves2bfloat162(hz, hw);
    Ll[0] = __halves2bfloat162(lx, ly); Ll[1] = __halves2bfloat162(lz, lw);
}

// ---------------------------------------------------------------------------
// Kernel B: HMMA split GEMM (R11 config: MT=64, NT=128, 3-buffer/2-deep ring).
// ---------------------------------------------------------------------------
#define BK_       32
#define GA_TILE   4096
#define GB_TILE   8192
#define GSTAGE    (2*GA_TILE + 2*GB_TILE)   // 24576
#define GEMM_SMEM_BYTES (3 * GSTAGE)        // 73728

__global__ void __launch_bounds__(256, 3) hmma_gemm_kernel(
    const float* __restrict__ bias, float* __restrict__ Cout, int mode)
{
    extern __shared__ __align__(128) char smem[];
    const __nv_bfloat16 *Ahi, *Alo, *Bhi, *Blo;
    if (mode == 0) { Ahi = g_Xhi; Alo = g_Xlo; Bhi = g_Wahi; Blo = g_Walo; }
    else           { Ahi = g_Ohi; Alo = g_Olo; Bhi = g_Wphi; Blo = g_Wplo; }

    uint32_t sb = smem_u32(smem);
    int tid = threadIdx.x, lane = tid & 31, wid = tid >> 5;
    int bm = blockIdx.y * 64, bn = blockIdx.x * 128;
    int wm = wid >> 2;
    int wn = wid & 3;

    auto prefetch = [&](int chunk, int stage) {
        int k0 = chunk * BK_;
        uint32_t sbase = sb + stage * GSTAGE;
#pragma unroll
        for (int it = 0; it < 6; it++) {
            int idx = tid + it * 256;
            if (idx < 512) {
                int row = idx >> 2, ch = idx & 3;
                int r = row & 63;
                const __nv_bfloat16* src =
                    ((row < 64) ? Ahi : Alo) + (size_t)(bm + r) * KD_ + k0 + ch * 8;
                CP_ASYNC16(sbase + ((row < 64) ? 0 : GA_TILE) + sw64(r, ch), src);
            } else {
                int j = idx - 512;
                int row = j >> 2, ch = j & 3;
                int r = row & 127;
                const __nv_bfloat16* src =
                    ((row < 128) ? Bhi : Blo) + (size_t)(bn + r) * KD_ + k0 + ch * 8;
                CP_ASYNC16(sbase + 2 * GA_TILE + ((row < 128) ? 0 : GB_TILE) + sw64(r, ch), src);
            }
        }
        CP_COMMIT();
    };

    float acc[2][4][4];
#pragma unroll
    for (int mi = 0; mi < 2; mi++)
#pragma unroll
        for (int ni = 0; ni < 4; ni++)
#pragma unroll
            for (int r = 0; r < 4; r++) acc[mi][ni][r] = 0.f;

    prefetch(0, 0);
    prefetch(1, 1);

    const int NCH = KD_ / BK_;   // 32
    for (int ch = 0; ch < NCH; ch++) {
        if (ch < NCH - 1) CP_WAIT1(); else CP_WAIT0();
        __syncthreads();

        int stage = ch - (ch / 3) * 3;
        uint32_t sbase = sb + stage * GSTAGE;
        uint32_t bbase = sbase + 2 * GA_TILE;

        if (ch + 2 < NCH) {
            int pst = ch + 2 - ((ch + 2) / 3) * 3;
            prefetch(ch + 2, pst);
        }

#pragma unroll
        for (int ks = 0; ks < 2; ks++) {
            uint32_t ah[2][4], al[2][4], bh[2][4], bl[2][4];
            int ac = ks * 2 + (lane >> 4);
#pragma unroll
            for (int mi = 0; mi < 2; mi++) {
                int ar = wm * 32 + mi * 16 + (lane & 15);
                uint32_t ad = sbase + sw64(ar, ac);
                LDSM_X4(ah[mi][0], ah[mi][1], ah[mi][2], ah[mi][3], ad);
                LDSM_X4(al[mi][0], al[mi][1], al[mi][2], al[mi][3], ad + GA_TILE);
            }
            int bc = ks * 2 + ((lane >> 3) & 1);
            int brl = ((lane >> 4) << 3) + (lane & 7);
#pragma unroll
            for (int np = 0; np < 2; np++) {
                int br = wn * 32 + np * 16 + brl;
                uint32_t bd = bbase + sw64(br, bc);
                LDSM_X4(bh[np][0], bh[np][1], bh[np][2], bh[np][3], bd);
                LDSM_X4(bl[np][0], bl[np][1], bl[np][2], bl[np][3], bd + GB_TILE);
            }
#pragma unroll
            for (int mi = 0; mi < 2; mi++)
#pragma unroll
                for (int np = 0; np < 2; np++) {
                    MMA_(acc[mi][2*np],   ah[mi][0], ah[mi][1], ah[mi][2], ah[mi][3], bh[np][0], bh[np][1]);
                    MMA_(acc[mi][2*np+1], ah[mi][0], ah[mi][1], ah[mi][2], ah[mi][3], bh[np][2], bh[np][3]);
                }
#pragma unroll
            for (int mi = 0; mi < 2; mi++)
#pragma unroll
                for (int np = 0; np < 2; np++) {
                    MMA_(acc[mi][2*np],   ah[mi][0], ah[mi][1], ah[mi][2], ah[mi][3], bl[np][0], bl[np][1]);
                    MMA_(acc[mi][2*np+1], ah[mi][0], ah[mi][1], ah[mi][2], ah[mi][3], bl[np][2], bl[np][3]);
                }
#pragma unroll
            for (int mi = 0; mi < 2; mi++)
#pragma unroll
                for (int np = 0; np < 2; np++) {
                    MMA_(acc[mi][2*np],   al[mi][0], al[mi][1], al[mi][2], al[mi][3], bh[np][0], bh[np][1]);
                    MMA_(acc[mi][2*np+1], al[mi][0], al[mi][1], al[mi][2], al[mi][3], bh[np][2], bh[np][3]);
                }
        }
    }

    int g = lane >> 2, t = lane & 3;
    if (mode == 0) {
#pragma unroll
        for (int mi = 0; mi < 2; mi++)
#pragma unroll
            for (int ni = 0; ni < 4; ni++) {
                int c0 = bn + wn * 32 + ni * 8 + t * 2;
                int seg = c0 >> 10, cn = c0 & 1023;
                int h = cn >> 6, d = cn & 63;
                float b0 = bias[c0], b1 = bias[c0 + 1];
#pragma unroll
                for (int half = 0; half < 2; half++) {
                    int m = bm + wm * 32 + mi * 16 + g + half * 8;
                    int b = m >> 11, tt = m & 2047;
                    float v0 = acc[mi][ni][half * 2 + 0] + b0;
                    float v1 = acc[mi][ni][half * 2 + 1] + b1;
                    if (seg == 0) { v0 *= 0.125f; v1 *= 0.125f; }
                    uint32_t hp = pack_bf16(v0, v1);
                    uint32_t lp = pack_bf16(v0 - bf16lo_f(hp), v1 - bf16hi_f(hp));
                    size_t o = (((size_t)(b * H_ + h) * T_) + tt) * HD_ + d;
                    __nv_bfloat16 *dh, *dl;
                    if (seg == 0)      { dh = g_Qh; dl = g_Ql; }
                    else if (seg == 1) { dh = g_Kh; dl = g_Kl; }
                    else               { dh = g_Vh; dl = g_Vl; }
                    *reinterpret_cast<uint32_t*>(dh + o) = hp;
                    *reinterpret_cast<uint32_t*>(dl + o) = lp;
                }
            }
    } else {
#pragma unroll
        for (int mi = 0; mi < 2; mi++)
#pragma unroll
            for (int ni = 0; ni < 4; ni++) {
                int r0 = bm + wm * 32 + mi * 16 + g;
                int c0 = bn + wn * 32 + ni * 8 + t * 2;
                float2 v0 = make_float2(acc[mi][ni][0] + bias[c0],
                                        acc[mi][ni][1] + bias[c0 + 1]);
                float2 v1 = make_float2(acc[mi][ni][2] + bias[c0],
                                        acc[mi][ni][3] + bias[c0 + 1]);
                *reinterpret_cast<float2*>(&Cout[(size_t)r0 * C_ + c0]) = v0;
                *reinterpret_cast<float2*>(&Cout[(size_t)(r0 + 8) * C_ + c0]) = v1;
            }
    }
}

// ---------------------------------------------------------------------------
// Kernel C: flash attention (R11 config: 128q/CTA as two 64-row subtiles,
// 2-stage KV ring, (128,2)). PV now uses 2 split terms (ph*vh + ph*vl);
// the P-lo correction is dropped (softmax is near-one-hot at this logit
// scale; aggregate error ~1e-4).
// ---------------------------------------------------------------------------
#define KV_TILE  8192
#define KV_STAGE (4 * KV_TILE)
#define ATTN_SMEM_BYTES (2 * KV_STAGE)      // 65536

__global__ void __launch_bounds__(128, 2) attn_hmma_kernel()
{
    extern __shared__ __align__(128) char smem[];
    uint32_t sb = smem_u32(smem);
    int tid = threadIdx.x, lane = tid & 31, wid = tid >> 5;
    int bh = blockIdx.y, q0 = blockIdx.x * 128;
    size_t bhbase = (size_t)bh * T_ * HD_;

    {
        const __nv_bfloat16* Qh = g_Qh + bhbase + (size_t)q0 * HD_;
        const __nv_bfloat16* Ql = g_Ql + bhbase + (size_t)q0 * HD_;
#pragma unroll
        for (int it = 0; it < 16; it++) {
            int idx = tid + it * 128;
            int tile = idx >> 10, within = idx & 1023;
            int row = within >> 3, ch = within & 7;
            const __nv_bfloat16* src = (tile ? Ql : Qh) + (size_t)row * HD_ + ch * 8;
            CP_ASYNC16(sb + tile * 16384 + sw128r(row, ch), src);
        }
        CP_COMMIT(); CP_WAIT0();
        __syncthreads();
    }

    uint32_t qh[2][4][4], ql[2][4][4];
#pragma unroll
    for (int sub = 0; sub < 2; sub++) {
        int arow = sub * 64 + wid * 16 + (lane & 15);
#pragma unroll
        for (int ks = 0; ks < 4; ks++) {
            int ac = ks * 2 + (lane >> 4);
            uint32_t addr = sb + sw128r(arow, ac);
            LDSM_X4(qh[sub][ks][0], qh[sub][ks][1], qh[sub][ks][2], qh[sub][ks][3], addr);
            LDSM_X4(ql[sub][ks][0], ql[sub][ks][1], ql[sub][ks][2], ql[sub][ks][3], addr + 16384);
        }
    }
    __syncthreads();

    const __nv_bfloat16 *Kh = g_Kh + bhbase, *Kl = g_Kl + bhbase;
    const __nv_bfloat16 *Vh = g_Vh + bhbase, *Vl = g_Vl + bhbase;

    auto kv_prefetch = [&](int kt) {
        uint32_t sbase = sb + (kt & 1) * KV_STAGE;
        int k0 = kt * 64;
#pragma unroll
        for (int it = 0; it < 16; it++) {
            int idx = tid + it * 128;
            int tile = idx >> 9, within = idx & 511;
            int row = within >> 3, ch = within & 7;
            const __nv_bfloat16* base =
                (tile == 0) ? Kh : (tile == 1) ? Kl : (tile == 2) ? Vh : Vl;
            CP_ASYNC16(sbase + tile * KV_TILE + sw128r(row, ch),
                       base + (size_t)(k0 + row) * HD_ + ch * 8);
        }
        CP_COMMIT();
    };

    float o[2][8][4];
#pragma unroll
    for (int sub = 0; sub < 2; sub++)
#pragma unroll
        for (int j = 0; j < 8; j++)
#pragma unroll
            for (int r = 0; r < 4; r++) o[sub][j][r] = 0.f;
    float mrow[2][2] = {{-1e30f, -1e30f}, {-1e30f, -1e30f}};
    float lrow[2][2] = {{0.f, 0.f}, {0.f, 0.f}};

    kv_prefetch(0);

    for (int kt = 0; kt < T_ / 64; kt++) {
        CP_WAIT0();
        __syncthreads();
        if (kt + 1 < T_ / 64) kv_prefetch(kt + 1);
        uint32_t sbase = sb + (kt & 1) * KV_STAGE;
        uint32_t vbase = sbase + 2 * KV_TILE;

        int brl = ((lane >> 4) << 3) + (lane & 7);
        int bc  = (lane >> 3) & 1;
        int vrow = lane & 15;
        int vc = lane >> 4;

#pragma unroll
        for (int sub = 0; sub < 2; sub++) {
            // ---- S = Q K^T (3 split terms — logit accuracy is load-bearing)
            float s[8][4];
#pragma unroll
            for (int j = 0; j < 8; j++)
#pragma unroll
                for (int r = 0; r < 4; r++) s[j][r] = 0.f;

#pragma unroll
            for (int ks = 0; ks < 4; ks++) {
                int lc = ks * 2 + bc;
#pragma unroll
                for (int npp = 0; npp < 2; npp++) {
                    int r0 = (2 * npp) * 16 + brl;
                    int r1 = (2 * npp + 1) * 16 + brl;
                    uint32_t a0 = sbase + sw128r(r0, lc);
                    uint32_t a1 = sbase + sw128r(r1, lc);
                    uint32_t kh0[4], kh1[4], kl0[4], kl1[4];
                    LDSM_X4(kh0[0], kh0[1], kh0[2], kh0[3], a0);
                    LDSM_X4(kh1[0], kh1[1], kh1[2], kh1[3], a1);
                    LDSM_X4(kl0[0], kl0[1], kl0[2], kl0[3], a0 + KV_TILE);
                    LDSM_X4(kl1[0], kl1[1], kl1[2], kl1[3], a1 + KV_TILE);
                    float* s0 = s[4*npp+0]; float* s1 = s[4*npp+1];
                    float* s2 = s[4*npp+2]; float* s3 = s[4*npp+3];
                    const uint32_t* QH = qh[sub][ks];
                    const uint32_t* QL = ql[sub][ks];
                    MMA_(s0, QH[0], QH[1], QH[2], QH[3], kh0[0], kh0[1]);
                    MMA_(s1, QH[0], QH[1], QH[2], QH[3], kh0[2], kh0[3]);
                    MMA_(s2, QH[0], QH[1], QH[2], QH[3], kh1[0], kh1[1]);
                    MMA_(s3, QH[0], QH[1], QH[2], QH[3], kh1[2], kh1[3]);
                    MMA_(s0, QH[0], QH[1], QH[2], QH[3], kl0[0], kl0[1]);
                    MMA_(s1, QH[0], QH[1], QH[2], QH[3], kl0[2], kl0[3]);
                    MMA_(s2, QH[0], QH[1], QH[2], QH[3], kl1[0], kl1[1]);
                    MMA_(s3, QH[0], QH[1], QH[2], QH[3], kl1[2], kl1[3]);
                    MMA_(s0, QL[0], QL[1], QL[2], QL[3], kh0[0], kh0[1]);
                    MMA_(s1, QL[0], QL[1], QL[2], QL[3], kh0[2], kh0[3]);
                    MMA_(s2, QL[0], QL[1], QL[2], QL[3], kh1[0], kh1[1]);
                    MMA_(s3, QL[0], QL[1], QL[2], QL[3], kh1[2], kh1[3]);
                }
            }

            // ---- online softmax ----
            float mt0 = -1e30f, mt1 = -1e30f;
#pragma unroll
            for (int j = 0; j < 8; j++) {
                mt0 = fmaxf(mt0, fmaxf(s[j][0], s[j][1]));
                mt1 = fmaxf(mt1, fmaxf(s[j][2], s[j][3]));
            }
            mt0 = fmaxf(mt0, __shfl_xor_sync(0xffffffffu, mt0, 1));
            mt0 = fmaxf(mt0, __shfl_xor_sync(0xffffffffu, mt0, 2));
            mt1 = fmaxf(mt1, __shfl_xor_sync(0xffffffffu, mt1, 1));
            mt1 = fmaxf(mt1, __shfl_xor_sync(0xffffffffu, mt1, 2));
            float mn0 = fmaxf(mrow[sub][0], mt0), mn1 = fmaxf(mrow[sub][1], mt1);
            float corr0 = fexp(mrow[sub][0] - mn0), corr1 = fexp(mrow[sub][1] - mn1);
            float sum0 = 0.f, sum1 = 0.f;
#pragma unroll
            for (int j = 0; j < 8; j++) {
                s[j][0] = fexp(s[j][0] - mn0);
                s[j][1] = fexp(s[j][1] - mn0);
                s[j][2] = fexp(s[j][2] - mn1);
                s[j][3] = fexp(s[j][3] - mn1);
                sum0 += s[j][0] + s[j][1];
                sum1 += s[j][2] + s[j][3];
            }
            sum0 += __shfl_xor_sync(0xffffffffu, sum0, 1);
            sum0 += __shfl_xor_sync(0xffffffffu, sum0, 2);
            sum1 += __shfl_xor_sync(0xffffffffu, sum1, 1);
            sum1 += __shfl_xor_sync(0xffffffffu, sum1, 2);
            lrow[sub][0] = lrow[sub][0] * corr0 + sum0;
            lrow[sub][1] = lrow[sub][1] * corr1 + sum1;
            mrow[sub][0] = mn0; mrow[sub][1] = mn1;
#pragma unroll
            for (int j = 0; j < 8; j++) {
                o[sub][j][0] *= corr0; o[sub][j][1] *= corr0;
                o[sub][j][2] *= corr1; o[sub][j][3] *= corr1;
            }

            // ---- O += P V  (2 terms: ph*vh + ph*vl; P-lo dropped) ----
#pragma unroll
            for (int ks = 0; ks < 4; ks++) {
                uint32_t ah0 = pack_bf16(s[2*ks][0],   s[2*ks][1]);
                uint32_t ah1 = pack_bf16(s[2*ks][2],   s[2*ks][3]);
                uint32_t ah2 = pack_bf16(s[2*ks+1][0], s[2*ks+1][1]);
                uint32_t ah3 = pack_bf16(s[2*ks+1][2], s[2*ks+1][3]);
                int row = ks * 16 + vrow;
#pragma unroll
                for (int jpp = 0; jpp < 2; jpp++) {
                    int lc0 = (2 * jpp) * 2 + vc;
                    int lc1 = (2 * jpp + 1) * 2 + vc;
                    uint32_t a0 = vbase + sw128r(row, lc0);
                    uint32_t a1 = vbase + sw128r(row, lc1);
                    uint32_t vh0[4], vh1[4], vl0[4], vl1[4];
                    LDSM_X4_T(vh0[0], vh0[1], vh0[2], vh0[3], a0);
                    LDSM_X4_T(vh1[0], vh1[1], vh1[2], vh1[3], a1);
                    LDSM_X4_T(vl0[0], vl0[1], vl0[2], vl0[3], a0 + KV_TILE);
                    LDSM_X4_T(vl1[0], vl1[1], vl1[2], vl1[3], a1 + KV_TILE);
                    float* o0 = o[sub][4*jpp+0]; float* o1 = o[sub][4*jpp+1];
                    float* o2 = o[sub][4*jpp+2]; float* o3 = o[sub][4*jpp+3];
                    MMA_(o0, ah0, ah1, ah2, ah3, vh0[0], vh0[1]);
                    MMA_(o1, ah0, ah1, ah2, ah3, vh0[2], vh0[3]);
                    MMA_(o2, ah0, ah1, ah2, ah3, vh1[0], vh1[1]);
                    MMA_(o3, ah0, ah1, ah2, ah3, vh1[2], vh1[3]);
                    MMA_(o0, ah0, ah1, ah2, ah3, vl0[0], vl0[1]);
                    MMA_(o1, ah0, ah1, ah2, ah3, vl0[2], vl0[3]);
                    MMA_(o2, ah0, ah1, ah2, ah3, vl1[0], vl1[1]);
                    MMA_(o3, ah0, ah1, ah2, ah3, vl1[2], vl1[3]);
                }
            }
        }
    }

    // ---- finalize ----
    int g = lane >> 2, t = lane & 3;
    int b = bh >> 4, h = bh & 15;
#pragma unroll
    for (int sub = 0; sub < 2; sub++) {
        float inv0 = 1.0f / lrow[sub][0], inv1 = 1.0f / lrow[sub][1];
        int row0 = q0 + sub * 64 + wid * 16 + g;
        size_t ob0 = ((size_t)(b * T_) + row0) * C_ + h * 64 + t * 2;
        size_t ob1 = ob0 + (size_t)8 * C_;
#pragma unroll
        for (int j = 0; j < 8; j++) {
            float v0 = o[sub][j][0] * inv0, v1 = o[sub][j][1] * inv0;
            float v2 = o[sub][j][2] * inv1, v3 = o[sub][j][3] * inv1;
            uint32_t h0 = pack_bf16(v0, v1);
            uint32_t h1 = pack_bf16(v2, v3);
            uint32_t l0p = pack_bf16(v0 - bf16lo_f(h0), v1 - bf16hi_f(h0));
            uint32_t l1p = pack_bf16(v2 - bf16lo_f(h1), v3 - bf16hi_f(h1));
            *reinterpret_cast<uint32_t*>(g_Ohi + ob0 + j * 8) = h0;
            *reinterpret_cast<uint32_t*>(g_Ohi + ob1 + j * 8) = h1;
            *reinterpret_cast<uint32_t*>(g_Olo + ob0 + j * 8) = l0p;
            *reinterpret_cast<uint32_t*>(g_Olo + ob1 + j * 8) = l1p;
        }
    }
}

// ---------------------------------------------------------------------------
extern "C" void kernel_launch(void* const* d_in, const int* in_sizes, int n_in,
                              void* d_out, int out_size)
{
    const float* x      = (const float*)d_in[0];
    const float* W_attn = (const float*)d_in[1];
    const float* b_attn = (const float*)d_in[2];
    const float* W_proj = (const float*)d_in[3];
    const float* b_proj = (const float*)d_in[4];
    float* out = (float*)d_out;

    cudaFuncSetAttribute(hmma_gemm_kernel,
                         cudaFuncAttributeMaxDynamicSharedMemorySize, GEMM_SMEM_BYTES);
    cudaFuncSetAttribute(attn_hmma_kernel,
                         cudaFuncAttributeMaxDynamicSharedMemorySize, ATTN_SMEM_BYTES);

    int splitBlocks = (NX4 + NWA4 + NWP4) / 256;
    split_all_kernel<<<splitBlocks, 256>>>(
        (const float4*)x, (const float4*)W_attn, (const float4*)W_proj);

    hmma_gemm_kernel<<<dim3(3 * C_ / 128, B_ * T_ / 64), 256, GEMM_SMEM_BYTES>>>(
        b_attn, nullptr, 0);

    attn_hmma_kernel<<<dim3(T_ / 128, BH_), 128, ATTN_SMEM_BYTES>>>();

    hmma_gemm_kernel<<<dim3(C_ / 128, B_ * T_ / 64), 256, GEMM_SMEM_BYTES>>>(
        b_proj, out, 1);
}

// round 14
// speedup vs baseline: 1.1856x; 1.0662x over previous
#include <cuda_runtime.h>
#include <cuda_bf16.h>
#include <cstdint>

#define B_  4
#define T_  2048
#define C_  1024
#define H_  16
#define HD_ 64
#define BH_ (B_*H_)
#define KD_ 1024

// ---------------------------------------------------------------------------
// Device-global scratch
// ---------------------------------------------------------------------------
__device__ __nv_bfloat16 g_Qh[(size_t)BH_*T_*HD_], g_Ql[(size_t)BH_*T_*HD_];
__device__ __nv_bfloat16 g_Kh[(size_t)BH_*T_*HD_], g_Kl[(size_t)BH_*T_*HD_];
__device__ __nv_bfloat16 g_Vh[(size_t)BH_*T_*HD_], g_Vl[(size_t)BH_*T_*HD_];

__device__ __nv_bfloat16 g_Xhi[(size_t)B_*T_*C_],   g_Xlo[(size_t)B_*T_*C_];
__device__ __nv_bfloat16 g_Wahi[(size_t)3*C_*C_],   g_Walo[(size_t)3*C_*C_];
__device__ __nv_bfloat16 g_Wphi[(size_t)C_*C_],     g_Wplo[(size_t)C_*C_];
__device__ __nv_bfloat16 g_Ohi[(size_t)B_*T_*C_],   g_Olo[(size_t)B_*T_*C_];

// ---------------------------------------------------------------------------
// Helpers
// ---------------------------------------------------------------------------
__device__ __forceinline__ uint32_t smem_u32(const void* p) {
    uint32_t a;
    asm("{ .reg .u64 t; cvta.to.shared.u64 t, %1; cvt.u32.u64 %0, t; }"
        : "=r"(a) : "l"(p));
    return a;
}

#define CP_ASYNC16(dst, src) \
    asm volatile("cp.async.cg.shared.global [%0], [%1], 16;" :: "r"(dst), "l"(src))
#define CP_COMMIT() asm volatile("cp.async.commit_group;" ::: "memory")
#define CP_WAIT1()  asm volatile("cp.async.wait_group 1;" ::: "memory")
#define CP_WAIT0()  asm volatile("cp.async.wait_group 0;" ::: "memory")

#define LDSM_X4(r0, r1, r2, r3, addr) \
    asm volatile("ldmatrix.sync.aligned.m8n8.x4.shared.b16 {%0,%1,%2,%3}, [%4];" \
        : "=r"(r0), "=r"(r1), "=r"(r2), "=r"(r3) : "r"(addr))
#define LDSM_X4_T(r0, r1, r2, r3, addr) \
    asm volatile("ldmatrix.sync.aligned.m8n8.x4.trans.shared.b16 {%0,%1,%2,%3}, [%4];" \
        : "=r"(r0), "=r"(r1), "=r"(r2), "=r"(r3) : "r"(addr))

#define MMA_(c, a0, a1, a2, a3, b0, b1) \
    asm volatile("mma.sync.aligned.m16n8k16.row.col.f32.bf16.bf16.f32 " \
        "{%0,%1,%2,%3}, {%4,%5,%6,%7}, {%8,%9}, {%0,%1,%2,%3};" \
        : "+f"((c)[0]), "+f"((c)[1]), "+f"((c)[2]), "+f"((c)[3]) \
        : "r"(a0), "r"(a1), "r"(a2), "r"(a3), "r"(b0), "r"(b1))

__device__ __forceinline__ uint32_t pack_bf16(float lo, float hi) {
    uint32_t r;
    asm("cvt.rn.bf16x2.f32 %0, %1, %2;" : "=r"(r) : "f"(hi), "f"(lo));
    return r;
}
__device__ __forceinline__ float bf16lo_f(uint32_t r) { return __int_as_float(r << 16); }
__device__ __forceinline__ float bf16hi_f(uint32_t r) { return __int_as_float(r & 0xffff0000u); }

// exp via MUFU pipe.
__device__ __forceinline__ float fexp(float x) {
    float y;
    asm("ex2.approx.ftz.f32 %0, %1;" : "=f"(y) : "f"(x * 1.4426950408889634f));
    return y;
}

// Swizzled 128B-row offset: phys chunk = ch ^ (row&7)
__device__ __forceinline__ uint32_t sw128r(int row, int ch) {
    return (uint32_t)(row * 128 + ((ch ^ (row & 7)) << 4));
}

// ---------------------------------------------------------------------------
// Kernel A: fused fp32 -> bf16 hi/lo split for x, W_attn, W_proj.
// ---------------------------------------------------------------------------
#define NX4   ((B_*T_*C_) / 4)
#define NWA4  ((3*C_*C_) / 4)
#define NWP4  ((C_*C_) / 4)

__global__ void __launch_bounds__(256) split_all_kernel(
    const float4* __restrict__ x, const float4* __restrict__ wa,
    const float4* __restrict__ wp)
{
    size_t i = (size_t)blockIdx.x * blockDim.x + threadIdx.x;
    const float4* src;
    __nv_bfloat16 *hi, *lo;
    size_t j;
    if (i < NX4)                 { src = x;  j = i;               hi = g_Xhi;  lo = g_Xlo;  }
    else if (i < NX4 + NWA4)     { src = wa; j = i - NX4;         hi = g_Wahi; lo = g_Walo; }
    else                         { src = wp; j = i - NX4 - NWA4;  hi = g_Wphi; lo = g_Wplo; }

    float4 v = src[j];
    __nv_bfloat16 hx = __float2bfloat16(v.x), hy = __float2bfloat16(v.y);
    __nv_bfloat16 hz = __float2bfloat16(v.z), hw = __float2bfloat16(v.w);
    __nv_bfloat16 lx = __float2bfloat16(v.x - __bfloat162float(hx));
    __nv_bfloat16 ly = __float2bfloat16(v.y - __bfloat162float(hy));
    __nv_bfloat16 lz = __float2bfloat16(v.z - __bfloat162float(hz));
    __nv_bfloat16 lw = __float2bfloat16(v.w - __bfloat162float(hw));
    __nv_bfloat162* Hh = reinterpret_cast<__nv_bfloat162*>(hi + 4 * j);
    __nv_bfloat162* Ll = reinterpret_cast<__nv_bfloat162*>(lo + 4 * j);
    Hh[0] = __halves2bfloat162(hx, hy); Hh[1] = __halves2bfloat162(hz, hw);
    Ll[0] = __halves2bfloat162(lx, ly); Ll[1] = __halves2bfloat162(lz, lw);
}

// ---------------------------------------------------------------------------
// Kernel B: HMMA split GEMM, BK=64 (128B rows, sw128r), 2-stage depth-1
// cp.async pipeline, one barrier per chunk, 16 chunks.
// Stage: Ahi[64x128B]=8K Alo=8K Bhi[128x128B]=16K Blo=16K -> 48K; x2 = 96K.
// ---------------------------------------------------------------------------
#define BK_       64
#define GA_TILE   8192
#define GB_TILE   16384
#define GSTAGE    (2*GA_TILE + 2*GB_TILE)   // 49152
#define GEMM_SMEM_BYTES (2 * GSTAGE)        // 98304

__global__ void __launch_bounds__(256, 2) hmma_gemm_kernel(
    const float* __restrict__ bias, float* __restrict__ Cout, int mode)
{
    extern __shared__ __align__(128) char smem[];
    const __nv_bfloat16 *Ahi, *Alo, *Bhi, *Blo;
    if (mode == 0) { Ahi = g_Xhi; Alo = g_Xlo; Bhi = g_Wahi; Blo = g_Walo; }
    else           { Ahi = g_Ohi; Alo = g_Olo; Bhi = g_Wphi; Blo = g_Wplo; }

    uint32_t sb = smem_u32(smem);
    int tid = threadIdx.x, lane = tid & 31, wid = tid >> 5;
    int bm = blockIdx.y * 64, bn = blockIdx.x * 128;
    int wm = wid >> 2;
    int wn = wid & 3;

    auto prefetch = [&](int chunk, int stage) {
        int k0 = chunk * BK_;
        uint32_t sbase = sb + stage * GSTAGE;
#pragma unroll
        for (int it = 0; it < 12; it++) {
            int idx = tid + it * 256;          // 0..3071
            if (idx < 1024) {                  // A: 128 rows (hi 64 + lo 64) x 8 ch
                int row = idx >> 3, ch = idx & 7;
                int r = row & 63;
                const __nv_bfloat16* src =
                    ((row < 64) ? Ahi : Alo) + (size_t)(bm + r) * KD_ + k0 + ch * 8;
                CP_ASYNC16(sbase + ((row < 64) ? 0 : GA_TILE) + sw128r(r, ch), src);
            } else {                           // B: 256 rows (hi 128 + lo 128) x 8 ch
                int j = idx - 1024;
                int row = j >> 3, ch = j & 7;
                int r = row & 127;
                const __nv_bfloat16* src =
                    ((row < 128) ? Bhi : Blo) + (size_t)(bn + r) * KD_ + k0 + ch * 8;
                CP_ASYNC16(sbase + 2 * GA_TILE + ((row < 128) ? 0 : GB_TILE) + sw128r(r, ch), src);
            }
        }
        CP_COMMIT();
    };

    float acc[2][4][4];
#pragma unroll
    for (int mi = 0; mi < 2; mi++)
#pragma unroll
        for (int ni = 0; ni < 4; ni++)
#pragma unroll
            for (int r = 0; r < 4; r++) acc[mi][ni][r] = 0.f;

    prefetch(0, 0);

    const int NCH = KD_ / BK_;   // 16
    for (int ch = 0; ch < NCH; ch++) {
        CP_WAIT0();
        __syncthreads();   // chunk ch visible; stage (ch+1)&1 retired by all warps

        uint32_t sbase = sb + (ch & 1) * GSTAGE;
        uint32_t bbase = sbase + 2 * GA_TILE;

        // prefetch next chunk into the other stage (retired at barrier above)
        if (ch + 1 < NCH) prefetch(ch + 1, (ch + 1) & 1);

#pragma unroll
        for (int ks = 0; ks < 4; ks++) {
            uint32_t ah[2][4], al[2][4], bh[2][4], bl[2][4];
            int ac = ks * 2 + (lane >> 4);
#pragma unroll
            for (int mi = 0; mi < 2; mi++) {
                int ar = wm * 32 + mi * 16 + (lane & 15);
                uint32_t ad = sbase + sw128r(ar, ac);
                LDSM_X4(ah[mi][0], ah[mi][1], ah[mi][2], ah[mi][3], ad);
                LDSM_X4(al[mi][0], al[mi][1], al[mi][2], al[mi][3], ad + GA_TILE);
            }
            int bc = ks * 2 + ((lane >> 3) & 1);
            int brl = ((lane >> 4) << 3) + (lane & 7);
#pragma unroll
            for (int np = 0; np < 2; np++) {
                int br = wn * 32 + np * 16 + brl;
                uint32_t bd = bbase + sw128r(br, bc);
                LDSM_X4(bh[np][0], bh[np][1], bh[np][2], bh[np][3], bd);
                LDSM_X4(bl[np][0], bl[np][1], bl[np][2], bl[np][3], bd + GB_TILE);
            }
#pragma unroll
            for (int mi = 0; mi < 2; mi++)
#pragma unroll
                for (int np = 0; np < 2; np++) {
                    MMA_(acc[mi][2*np],   ah[mi][0], ah[mi][1], ah[mi][2], ah[mi][3], bh[np][0], bh[np][1]);
                    MMA_(acc[mi][2*np+1], ah[mi][0], ah[mi][1], ah[mi][2], ah[mi][3], bh[np][2], bh[np][3]);
                }
#pragma unroll
            for (int mi = 0; mi < 2; mi++)
#pragma unroll
                for (int np = 0; np < 2; np++) {
                    MMA_(acc[mi][2*np],   ah[mi][0], ah[mi][1], ah[mi][2], ah[mi][3], bl[np][0], bl[np][1]);
                    MMA_(acc[mi][2*np+1], ah[mi][0], ah[mi][1], ah[mi][2], ah[mi][3], bl[np][2], bl[np][3]);
                }
#pragma unroll
            for (int mi = 0; mi < 2; mi++)
#pragma unroll
                for (int np = 0; np < 2; np++) {
                    MMA_(acc[mi][2*np],   al[mi][0], al[mi][1], al[mi][2], al[mi][3], bh[np][0], bh[np][1]);
                    MMA_(acc[mi][2*np+1], al[mi][0], al[mi][1], al[mi][2], al[mi][3], bh[np][2], bh[np][3]);
                }
        }
    }

    int g = lane >> 2, t = lane & 3;
    if (mode == 0) {
#pragma unroll
        for (int mi = 0; mi < 2; mi++)
#pragma unroll
            for (int ni = 0; ni < 4; ni++) {
                int c0 = bn + wn * 32 + ni * 8 + t * 2;
                int seg = c0 >> 10, cn = c0 & 1023;
                int h = cn >> 6, d = cn & 63;
                float b0 = bias[c0], b1 = bias[c0 + 1];
#pragma unroll
                for (int half = 0; half < 2; half++) {
                    int m = bm + wm * 32 + mi * 16 + g + half * 8;
                    int b = m >> 11, tt = m & 2047;
                    float v0 = acc[mi][ni][half * 2 + 0] + b0;
                    float v1 = acc[mi][ni][half * 2 + 1] + b1;
                    if (seg == 0) { v0 *= 0.125f; v1 *= 0.125f; }
                    uint32_t hp = pack_bf16(v0, v1);
                    uint32_t lp = pack_bf16(v0 - bf16lo_f(hp), v1 - bf16hi_f(hp));
                    size_t o = (((size_t)(b * H_ + h) * T_) + tt) * HD_ + d;
                    __nv_bfloat16 *dh, *dl;
                    if (seg == 0)      { dh = g_Qh; dl = g_Ql; }
                    else if (seg == 1) { dh = g_Kh; dl = g_Kl; }
                    else               { dh = g_Vh; dl = g_Vl; }
                    *reinterpret_cast<uint32_t*>(dh + o) = hp;
                    *reinterpret_cast<uint32_t*>(dl + o) = lp;
                }
            }
    } else {
#pragma unroll
        for (int mi = 0; mi < 2; mi++)
#pragma unroll
            for (int ni = 0; ni < 4; ni++) {
                int r0 = bm + wm * 32 + mi * 16 + g;
                int c0 = bn + wn * 32 + ni * 8 + t * 2;
                float2 v0 = make_float2(acc[mi][ni][0] + bias[c0],
                                        acc[mi][ni][1] + bias[c0 + 1]);
                float2 v1 = make_float2(acc[mi][ni][2] + bias[c0],
                                        acc[mi][ni][3] + bias[c0 + 1]);
                *reinterpret_cast<float2*>(&Cout[(size_t)r0 * C_ + c0]) = v0;
                *reinterpret_cast<float2*>(&Cout[(size_t)(r0 + 8) * C_ + c0]) = v1;
            }
    }
}

// ---------------------------------------------------------------------------
// Kernel C: flash attention (unchanged from Round 13).
// ---------------------------------------------------------------------------
#define KV_TILE  8192
#define KV_STAGE (4 * KV_TILE)
#define ATTN_SMEM_BYTES (2 * KV_STAGE)      // 65536

__global__ void __launch_bounds__(128, 2) attn_hmma_kernel()
{
    extern __shared__ __align__(128) char smem[];
    uint32_t sb = smem_u32(smem);
    int tid = threadIdx.x, lane = tid & 31, wid = tid >> 5;
    int bh = blockIdx.y, q0 = blockIdx.x * 128;
    size_t bhbase = (size_t)bh * T_ * HD_;

    {
        const __nv_bfloat16* Qh = g_Qh + bhbase + (size_t)q0 * HD_;
        const __nv_bfloat16* Ql = g_Ql + bhbase + (size_t)q0 * HD_;
#pragma unroll
        for (int it = 0; it < 16; it++) {
            int idx = tid + it * 128;
            int tile = idx >> 10, within = idx & 1023;
            int row = within >> 3, ch = within & 7;
            const __nv_bfloat16* src = (tile ? Ql : Qh) + (size_t)row * HD_ + ch * 8;
            CP_ASYNC16(sb + tile * 16384 + sw128r(row, ch), src);
        }
        CP_COMMIT(); CP_WAIT0();
        __syncthreads();
    }

    uint32_t qh[2][4][4], ql[2][4][4];
#pragma unroll
    for (int sub = 0; sub < 2; sub++) {
        int arow = sub * 64 + wid * 16 + (lane & 15);
#pragma unroll
        for (int ks = 0; ks < 4; ks++) {
            int ac = ks * 2 + (lane >> 4);
            uint32_t addr = sb + sw128r(arow, ac);
            LDSM_X4(qh[sub][ks][0], qh[sub][ks][1], qh[sub][ks][2], qh[sub][ks][3], addr);
            LDSM_X4(ql[sub][ks][0], ql[sub][ks][1], ql[sub][ks][2], ql[sub][ks][3], addr + 16384);
        }
    }
    __syncthreads();

    const __nv_bfloat16 *Kh = g_Kh + bhbase, *Kl = g_Kl + bhbase;
    const __nv_bfloat16 *Vh = g_Vh + bhbase, *Vl = g_Vl + bhbase;

    auto kv_prefetch = [&](int kt) {
        uint32_t sbase = sb + (kt & 1) * KV_STAGE;
        int k0 = kt * 64;
#pragma unroll
        for (int it = 0; it < 16; it++) {
            int idx = tid + it * 128;
            int tile = idx >> 9, within = idx & 511;
            int row = within >> 3, ch = within & 7;
            const __nv_bfloat16* base =
                (tile == 0) ? Kh : (tile == 1) ? Kl : (tile == 2) ? Vh : Vl;
            CP_ASYNC16(sbase + tile * KV_TILE + sw128r(row, ch),
                       base + (size_t)(k0 + row) * HD_ + ch * 8);
        }
        CP_COMMIT();
    };

    float o[2][8][4];
#pragma unroll
    for (int sub = 0; sub < 2; sub++)
#pragma unroll
        for (int j = 0; j < 8; j++)
#pragma unroll
            for (int r = 0; r < 4; r++) o[sub][j][r] = 0.f;
    float mrow[2][2] = {{-1e30f, -1e30f}, {-1e30f, -1e30f}};
    float lrow[2][2] = {{0.f, 0.f}, {0.f, 0.f}};

    kv_prefetch(0);

    for (int kt = 0; kt < T_ / 64; kt++) {
        CP_WAIT0();
        __syncthreads();
        if (kt + 1 < T_ / 64) kv_prefetch(kt + 1);
        uint32_t sbase = sb + (kt & 1) * KV_STAGE;
        uint32_t vbase = sbase + 2 * KV_TILE;

        int brl = ((lane >> 4) << 3) + (lane & 7);
        int bc  = (lane >> 3) & 1;
        int vrow = lane & 15;
        int vc = lane >> 4;

#pragma unroll
        for (int sub = 0; sub < 2; sub++) {
            float s[8][4];
#pragma unroll
            for (int j = 0; j < 8; j++)
#pragma unroll
                for (int r = 0; r < 4; r++) s[j][r] = 0.f;

#pragma unroll
            for (int ks = 0; ks < 4; ks++) {
                int lc = ks * 2 + bc;
#pragma unroll
                for (int npp = 0; npp < 2; npp++) {
                    int r0 = (2 * npp) * 16 + brl;
                    int r1 = (2 * npp + 1) * 16 + brl;
                    uint32_t a0 = sbase + sw128r(r0, lc);
                    uint32_t a1 = sbase + sw128r(r1, lc);
                    uint32_t kh0[4], kh1[4], kl0[4], kl1[4];
                    LDSM_X4(kh0[0], kh0[1], kh0[2], kh0[3], a0);
                    LDSM_X4(kh1[0], kh1[1], kh1[2], kh1[3], a1);
                    LDSM_X4(kl0[0], kl0[1], kl0[2], kl0[3], a0 + KV_TILE);
                    LDSM_X4(kl1[0], kl1[1], kl1[2], kl1[3], a1 + KV_TILE);
                    float* s0 = s[4*npp+0]; float* s1 = s[4*npp+1];
                    float* s2 = s[4*npp+2]; float* s3 = s[4*npp+3];
                    const uint32_t* QH = qh[sub][ks];
                    const uint32_t* QL = ql[sub][ks];
                    MMA_(s0, QH[0], QH[1], QH[2], QH[3], kh0[0], kh0[1]);
                    MMA_(s1, QH[0], QH[1], QH[2], QH[3], kh0[2], kh0[3]);
                    MMA_(s2, QH[0], QH[1], QH[2], QH[3], kh1[0], kh1[1]);
                    MMA_(s3, QH[0], QH[1], QH[2], QH[3], kh1[2], kh1[3]);
                    MMA_(s0, QH[0], QH[1], QH[2], QH[3], kl0[0], kl0[1]);
                    MMA_(s1, QH[0], QH[1], QH[2], QH[3], kl0[2], kl0[3]);
                    MMA_(s2, QH[0], QH[1], QH[2], QH[3], kl1[0], kl1[1]);
                    MMA_(s3, QH[0], QH[1], QH[2], QH[3], kl1[2], kl1[3]);
                    MMA_(s0, QL[0], QL[1], QL[2], QL[3], kh0[0], kh0[1]);
                    MMA_(s1, QL[0], QL[1], QL[2], QL[3], kh0[2], kh0[3]);
                    MMA_(s2, QL[0], QL[1], QL[2], QL[3], kh1[0], kh1[1]);
                    MMA_(s3, QL[0], QL[1], QL[2], QL[3], kh1[2], kh1[3]);
                }
            }

            float mt0 = -1e30f, mt1 = -1e30f;
#pragma unroll
            for (int j = 0; j < 8; j++) {
                mt0 = fmaxf(mt0, fmaxf(s[j][0], s[j][1]));
                mt1 = fmaxf(mt1, fmaxf(s[j][2], s[j][3]));
            }
            mt0 = fmaxf(mt0, __shfl_xor_sync(0xffffffffu, mt0, 1));
            mt0 = fmaxf(mt0, __shfl_xor_sync(0xffffffffu, mt0, 2));
            mt1 = fmaxf(mt1, __shfl_xor_sync(0xffffffffu, mt1, 1));
            mt1 = fmaxf(mt1, __shfl_xor_sync(0xffffffffu, mt1, 2));
            float mn0 = fmaxf(mrow[sub][0], mt0), mn1 = fmaxf(mrow[sub][1], mt1);
            float corr0 = fexp(mrow[sub][0] - mn0), corr1 = fexp(mrow[sub][1] - mn1);
            float sum0 = 0.f, sum1 = 0.f;
#pragma unroll
            for (int j = 0; j < 8; j++) {
                s[j][0] = fexp(s[j][0] - mn0);
                s[j][1] = fexp(s[j][1] - mn0);
                s[j][2] = fexp(s[j][2] - mn1);
                s[j][3] = fexp(s[j][3] - mn1);
                sum0 += s[j][0] + s[j][1];
                sum1 += s[j][2] + s[j][3];
            }
            sum0 += __shfl_xor_sync(0xffffffffu, sum0, 1);
            sum0 += __shfl_xor_sync(0xffffffffu, sum0, 2);
            sum1 += __shfl_xor_sync(0xffffffffu, sum1, 1);
            sum1 += __shfl_xor_sync(0xffffffffu, sum1, 2);
            lrow[sub][0] = lrow[sub][0] * corr0 + sum0;
            lrow[sub][1] = lrow[sub][1] * corr1 + sum1;
            mrow[sub][0] = mn0; mrow[sub][1] = mn1;
#pragma unroll
            for (int j = 0; j < 8; j++) {
                o[sub][j][0] *= corr0; o[sub][j][1] *= corr0;
                o[sub][j][2] *= corr1; o[sub][j][3] *= corr1;
            }

#pragma unroll
            for (int ks = 0; ks < 4; ks++) {
                uint32_t ah0 = pack_bf16(s[2*ks][0],   s[2*ks][1]);
                uint32_t ah1 = pack_bf16(s[2*ks][2],   s[2*ks][3]);
                uint32_t ah2 = pack_bf16(s[2*ks+1][0], s[2*ks+1][1]);
                uint32_t ah3 = pack_bf16(s[2*ks+1][2], s[2*ks+1][3]);
                int row = ks * 16 + vrow;
#pragma unroll
                for (int jpp = 0; jpp < 2; jpp++) {
                    int lc0 = (2 * jpp) * 2 + vc;
                    int lc1 = (2 * jpp + 1) * 2 + vc;
                    uint32_t a0 = vbase + sw128r(row, lc0);
                    uint32_t a1 = vbase + sw128r(row, lc1);
                    uint32_t vh0[4], vh1[4], vl0[4], vl1[4];
                    LDSM_X4_T(vh0[0], vh0[1], vh0[2], vh0[3], a0);
                    LDSM_X4_T(vh1[0], vh1[1], vh1[2], vh1[3], a1);
                    LDSM_X4_T(vl0[0], vl0[1], vl0[2], vl0[3], a0 + KV_TILE);
                    LDSM_X4_T(vl1[0], vl1[1], vl1[2], vl1[3], a1 + KV_TILE);
                    float* o0 = o[sub][4*jpp+0]; float* o1 = o[sub][4*jpp+1];
                    float* o2 = o[sub][4*jpp+2]; float* o3 = o[sub][4*jpp+3];
                    MMA_(o0, ah0, ah1, ah2, ah3, vh0[0], vh0[1]);
                    MMA_(o1, ah0, ah1, ah2, ah3, vh0[2], vh0[3]);
                    MMA_(o2, ah0, ah1, ah2, ah3, vh1[0], vh1[1]);
                    MMA_(o3, ah0, ah1, ah2, ah3, vh1[2], vh1[3]);
                    MMA_(o0, ah0, ah1, ah2, ah3, vl0[0], vl0[1]);
                    MMA_(o1, ah0, ah1, ah2, ah3, vl0[2], vl0[3]);
                    MMA_(o2, ah0, ah1, ah2, ah3, vl1[0], vl1[1]);
                    MMA_(o3, ah0, ah1, ah2, ah3, vl1[2], vl1[3]);
                }
            }
        }
    }

    int g = lane >> 2, t = lane & 3;
    int b = bh >> 4, h = bh & 15;
#pragma unroll
    for (int sub = 0; sub < 2; sub++) {
        float inv0 = 1.0f / lrow[sub][0], inv1 = 1.0f / lrow[sub][1];
        int row0 = q0 + sub * 64 + wid * 16 + g;
        size_t ob0 = ((size_t)(b * T_) + row0) * C_ + h * 64 + t * 2;
        size_t ob1 = ob0 + (size_t)8 * C_;
#pragma unroll
        for (int j = 0; j < 8; j++) {
            float v0 = o[sub][j][0] * inv0, v1 = o[sub][j][1] * inv0;
            float v2 = o[sub][j][2] * inv1, v3 = o[sub][j][3] * inv1;
            uint32_t h0 = pack_bf16(v0, v1);
            uint32_t h1 = pack_bf16(v2, v3);
            uint32_t l0p = pack_bf16(v0 - bf16lo_f(h0), v1 - bf16hi_f(h0));
            uint32_t l1p = pack_bf16(v2 - bf16lo_f(h1), v3 - bf16hi_f(h1));
            *reinterpret_cast<uint32_t*>(g_Ohi + ob0 + j * 8) = h0;
            *reinterpret_cast<uint32_t*>(g_Ohi + ob1 + j * 8) = h1;
            *reinterpret_cast<uint32_t*>(g_Olo + ob0 + j * 8) = l0p;
            *reinterpret_cast<uint32_t*>(g_Olo + ob1 + j * 8) = l1p;
        }
    }
}

// ---------------------------------------------------------------------------
extern "C" void kernel_launch(void* const* d_in, const int* in_sizes, int n_in,
                              void* d_out, int out_size)
{
    const float* x      = (const float*)d_in[0];
    const float* W_attn = (const float*)d_in[1];
    const float* b_attn = (const float*)d_in[2];
    const float* W_proj = (const float*)d_in[3];
    const float* b_proj = (const float*)d_in[4];
    float* out = (float*)d_out;

    cudaFuncSetAttribute(hmma_gemm_kernel,
                         cudaFuncAttributeMaxDynamicSharedMemorySize, GEMM_SMEM_BYTES);
    cudaFuncSetAttribute(attn_hmma_kernel,
                         cudaFuncAttributeMaxDynamicSharedMemorySize, ATTN_SMEM_BYTES);

    int splitBlocks = (NX4 + NWA4 + NWP4) / 256;
    split_all_kernel<<<splitBlocks, 256>>>(
        (const float4*)x, (const float4*)W_attn, (const float4*)W_proj);

    hmma_gemm_kernel<<<dim3(3 * C_ / 128, B_ * T_ / 64), 256, GEMM_SMEM_BYTES>>>(
        b_attn, nullptr, 0);

    attn_hmma_kernel<<<dim3(T_ / 128, BH_), 128, ATTN_SMEM_BYTES>>>();

    hmma_gemm_kernel<<<dim3(C_ / 128, B_ * T_ / 64), 256, GEMM_SMEM_BYTES>>>(
        b_proj, out, 1);
}